// round 13
// baseline (speedup 1.0000x reference)
#include <cuda_runtime.h>
#include <cuda_bf16.h>
#include <cstdint>

// Problem constants
#define B_    32
#define N_    64
#define H_    32
#define KTOT  1280            // D*E
#define NROWS (B_*N_*N_)      // 131072
#define NP1   65
#define CELLS (NP1*NP1)       // 4225
#define TILE_M 128
#define NTILES (NROWS / TILE_M)   // 1024
#define NWORK  256                // static: 4 tiles per CTA (R10 champion schedule)
#define SB    1288            // Bs row stride (bf16): (SB/2)%32==4 -> conflict-free
#define SMEM_BYTES (H_ * SB * 2 + 2048 * 4)   // Bs (82,432) + W_edge stage (8,192)

__device__ __forceinline__ uint32_t f2b2(float x, float y) {
    __nv_bfloat162 b = __floats2bfloat162_rn(x, y);
    return *reinterpret_cast<uint32_t*>(&b);
}

// ---------------------------------------------------------------------------
// Single fused kernel:
//   prologue: border writes (blocks 0..16) + per-CTA B fold (W3*W_edge -> SMEM,
//             with the sigma k-permutation baked in so a contiguous LDG.128
//             float4 of A is a valid mma.m16n8k16 fragment)
//   main:     static 4-tile GEMM + fused interior assembly, zero barriers.
// ---------------------------------------------------------------------------
__global__ void __launch_bounds__(256, 2) fused_k(const float* __restrict__ A,
                                                  const float* __restrict__ attn_bias,
                                                  const int*   __restrict__ spatial_pos,
                                                  const float* __restrict__ spatial_emb,
                                                  const float* __restrict__ W_edge,
                                                  const float* __restrict__ edw,
                                                  const float* __restrict__ vd,
                                                  float*       __restrict__ out) {
    extern __shared__ __nv_bfloat16 Bs[];                 // [32][SB] bf16
    float* Ws = (float*)(Bs + H_ * SB);                   // [32][64] f32 W_edge

    const int tid  = threadIdx.x;
    const int lane = tid & 31;
    const int q = lane >> 2;      // 0..7
    const int t = lane & 3;       // 0..3

    // ---- border cells (i==0 or j==0): disjoint from interior, no hazard ----
    if (blockIdx.x < 17) {
        int o = blockIdx.x * 256 + tid;        // b*129 + c
        if (o < B_ * 129) {
            int c = o % 129;
            int b = o / 129;
            int i = (c < NP1) ? 0 : (c - 64);
            int j = (c < NP1) ? c : 0;
            float a2 = 2.f * attn_bias[(b * NP1 + i) * NP1 + j];
            float* op = out + (size_t)b * H_ * CELLS + (size_t)i * NP1 + j;
#pragma unroll 8
            for (int h = 0; h < H_; h++)
                op[(size_t)h * CELLS] = a2 + vd[h];
        }
    }

    // ---- stage W_edge (32x64 f32 = 512 float4) ----
#pragma unroll
    for (int i = 0; i < 2; i++) {
        int idx = tid + i * 256;
        ((float4*)Ws)[idx] = ((const float4*)W_edge)[idx];
    }
    __syncthreads();

    // ---- compute B in-CTA: 640 (dd,g) pairs, 64 e-values each ----
    // M[g][dd*64+e] = sum_h edw[dd*1024+h*32+g] * W_edge[h][e]
    for (int p = tid; p < 640; p += 256) {
        const int dd = p >> 5;
        const int g  = p & 31;
        float coef[32];
#pragma unroll
        for (int h = 0; h < 32; h++)
            coef[h] = __ldg(&edw[dd * 1024 + h * 32 + g]);   // lane-coalesced (g = lane)
#pragma unroll
        for (int e0 = 0; e0 < 64; e0 += 8) {
            float ac[8];
#pragma unroll
            for (int x = 0; x < 8; x++) ac[x] = 0.f;
#pragma unroll
            for (int h = 0; h < 32; h++) {
                float4 w0 = *(const float4*)(Ws + h * 64 + e0);
                float4 w1 = *(const float4*)(Ws + h * 64 + e0 + 4);
                float c = coef[h];
                ac[0] += c * w0.x; ac[1] += c * w0.y; ac[2] += c * w0.z; ac[3] += c * w0.w;
                ac[4] += c * w1.x; ac[5] += c * w1.y; ac[6] += c * w1.z; ac[7] += c * w1.w;
            }
#pragma unroll
            for (int x = 0; x < 8; x++) {
                int k   = dd * 64 + e0 + x;
                int o16 = k & 15;
                int bse = k & ~15;
                int bb  = ((o16 & 3) < 2) ? ((o16 >> 2) * 2 + (o16 & 1))
                                          : (8 + (o16 >> 2) * 2 + (o16 & 1));
                Bs[g * SB + bse + bb] = __float2bfloat16(ac[x]);
            }
        }
    }
    __syncthreads();   // only barrier before the main loop

    // ---- main loop: R10 champion (static 4 tiles, zero barriers) ----
    for (int w = 0; w < NTILES / NWORK; w++) {
        const int tile = blockIdx.x + w * NWORK;
        const int warp = tid >> 5;
        const int row0 = tile * TILE_M + warp * 16;

        const float* ap0 = A + (size_t)(row0 + q) * KTOT + t * 4;
        const float* ap1 = ap0 + (size_t)8 * KTOT;

        float acc[4][4];
#pragma unroll
        for (int i = 0; i < 4; i++)
#pragma unroll
            for (int j = 0; j < 4; j++) acc[i][j] = 0.f;

        float4 f[2][2][2];   // [buf][u][rowhalf]
        auto loadA = [&](float4 (&dst)[2][2], int kc) {
#pragma unroll
            for (int u = 0; u < 2; u++) {
                dst[u][0] = *(const float4*)(ap0 + kc + u * 16);
                dst[u][1] = *(const float4*)(ap1 + kc + u * 16);
            }
        };

        loadA(f[0], 0);
        loadA(f[1], 32);

#pragma unroll 2
        for (int s2 = 0; s2 < 40; s2++) {          // k32 steps, depth-2 pipeline
            const int kc  = s2 * 32;
            const int cur = s2 & 1;
            uint32_t a[2][4];
#pragma unroll
            for (int u = 0; u < 2; u++) {
                float4 fq  = f[cur][u][0];
                float4 fq8 = f[cur][u][1];
                a[u][0] = f2b2(fq.x,  fq.y);
                a[u][1] = f2b2(fq8.x, fq8.y);
                a[u][2] = f2b2(fq.z,  fq.w);
                a[u][3] = f2b2(fq8.z, fq8.w);
            }
            if (kc + 64 < KTOT) loadA(f[cur], kc + 64);
#pragma unroll
            for (int u = 0; u < 2; u++) {
                const int ks = kc + u * 16;
#pragma unroll
                for (int nb = 0; nb < 4; nb++) {
                    const __nv_bfloat16* bp = Bs + (nb * 8 + q) * SB + ks + t * 2;
                    uint32_t b0 = *(const uint32_t*)bp;
                    uint32_t b1 = *(const uint32_t*)(bp + 8);
                    asm volatile(
                        "mma.sync.aligned.m16n8k16.row.col.f32.bf16.bf16.f32 "
                        "{%0,%1,%2,%3}, {%4,%5,%6,%7}, {%8,%9}, {%0,%1,%2,%3};"
                        : "+f"(acc[nb][0]), "+f"(acc[nb][1]),
                          "+f"(acc[nb][2]), "+f"(acc[nb][3])
                        : "r"(a[u][0]), "r"(a[u][1]), "r"(a[u][2]), "r"(a[u][3]),
                          "r"(b0), "r"(b1));
                }
            }
        }

        // Fused epilogue: final output for the two rows this lane owns.
        const int rq = row0 + q;
#pragma unroll
        for (int rr = 0; rr < 2; rr++) {
            const int r  = rq + rr * 8;
            const int b  = r >> 12;
            const int ij = r & 4095;
            const int ii = ij >> 6;
            const int jj = ij & 63;
            float ab2 = 2.f * __ldg(&attn_bias[(b * NP1 + ii + 1) * NP1 + jj + 1]);
            int s = __ldg(&spatial_pos[r]);
            int sp = (s <= 1) ? 1 : (s - 1);
            sp = min(sp, 20);
            float inv = 1.f / (float)sp;
            const float* se = spatial_emb + (size_t)s * H_;
            float* ob = out + (size_t)b * H_ * CELLS + (size_t)(ii + 1) * NP1 + (jj + 1);
#pragma unroll
            for (int nb = 0; nb < 4; nb++) {
                const int g0 = nb * 8 + t * 2;
                float2 sev = *(const float2*)(se + g0);
                ob[(size_t)(g0 + 0) * CELLS] = ab2 + sev.x + acc[nb][rr * 2 + 0] * inv;
                ob[(size_t)(g0 + 1) * CELLS] = ab2 + sev.y + acc[nb][rr * 2 + 1] * inv;
            }
        }
        // no barrier between tiles: B immutable, warps independent
    }
}

// ---------------------------------------------------------------------------
extern "C" void kernel_launch(void* const* d_in, const int* in_sizes, int n_in,
                              void* d_out, int out_size) {
    // metadata order: node_features, attn_bias, spatial_pos, edge_input,
    //                 attn_edge_type, W_edge, spatial_emb, vd_weight, edge_dis_weight
    const float* attn_bias   = (const float*)d_in[1];
    const int*   spatial_pos = (const int*)  d_in[2];
    const float* edge_input  = (const float*)d_in[3];
    const float* W_edge      = (const float*)d_in[5];
    const float* spatial_emb = (const float*)d_in[6];
    const float* vd          = (const float*)d_in[7];
    const float* edw         = (const float*)d_in[8];
    float* out = (float*)d_out;

    static bool attr_set = false;
    if (!attr_set) {
        cudaFuncSetAttribute(fused_k, cudaFuncAttributeMaxDynamicSharedMemorySize, SMEM_BYTES);
        attr_set = true;
    }

    fused_k<<<NWORK, 256, SMEM_BYTES>>>(edge_input, attn_bias, spatial_pos,
                                        spatial_emb, W_edge, edw, vd, out);
}

// round 14
// speedup vs baseline: 1.1734x; 1.1734x over previous
#include <cuda_runtime.h>
#include <cuda_bf16.h>
#include <cstdint>

// Problem constants
#define B_    32
#define N_    64
#define H_    32
#define KTOT  1280            // D*E
#define NROWS (B_*N_*N_)      // 131072
#define NP1   65
#define CELLS (NP1*NP1)       // 4225
#define TILE_M 128
#define NTILES (NROWS / TILE_M)   // 1024
#define NWORK  256                // static: 4 tiles per CTA (champion schedule)
#define SB    1288            // Bs row stride (bf16): (SB/2)%32==4 -> conflict-free
#define SMEM_BYTES (H_ * SB * 2)  // 82,432 B

// Scratch (allocation-free contract: device globals)
__device__ __nv_bfloat16 g_M[H_ * KTOT];   // 80 KB folded W3*W_edge, [g][k'] (k-permuted)

// ---------------------------------------------------------------------------
// Kernel 1 (merged): blocks < 160 compute g_M (4-way ILP on the h-chain);
// blocks >= 160 fill borders.
// ---------------------------------------------------------------------------
__global__ void prep_M(const float* __restrict__ W_edge, const float* __restrict__ edw,
                       const float* __restrict__ attn_bias, const float* __restrict__ vd,
                       float* __restrict__ out) {
    if (blockIdx.x >= 160) {
        int o = (blockIdx.x - 160) * blockDim.x + threadIdx.x;   // b*129 + c
        if (o >= B_ * 129) return;
        int c = o % 129;
        int b = o / 129;
        int i = (c < NP1) ? 0 : (c - 64);
        int j = (c < NP1) ? c : 0;
        float a2 = 2.f * attn_bias[(b * NP1 + i) * NP1 + j];
        float* op = out + (size_t)b * H_ * CELLS + (size_t)i * NP1 + j;
#pragma unroll 8
        for (int h = 0; h < H_; h++)
            op[(size_t)h * CELLS] = a2 + vd[h];
        return;
    }
    int idx = blockIdx.x * blockDim.x + threadIdx.x;
    if (idx >= H_ * KTOT) return;
    int g  = idx / KTOT;
    int kp = idx - g * KTOT;                 // permuted position k'
    int bse = kp & ~15;
    int b   = kp & 15;
    int o   = (b < 8) ? ((b >> 1) * 4 + (b & 1))
                      : (((b - 8) >> 1) * 4 + 2 + (b & 1));
    int k  = bse + o;                        // original k
    int dd = k >> 6;
    int e  = k & 63;
    float s0 = 0.f, s1 = 0.f, s2 = 0.f, s3 = 0.f;
#pragma unroll
    for (int h = 0; h < 32; h += 4) {
        s0 += edw[dd * 1024 + (h + 0) * 32 + g] * W_edge[(h + 0) * 64 + e];
        s1 += edw[dd * 1024 + (h + 1) * 32 + g] * W_edge[(h + 1) * 64 + e];
        s2 += edw[dd * 1024 + (h + 2) * 32 + g] * W_edge[(h + 2) * 64 + e];
        s3 += edw[dd * 1024 + (h + 3) * 32 + g] * W_edge[(h + 3) * 64 + e];
    }
    g_M[g * KTOT + kp] = __float2bfloat16((s0 + s1) + (s2 + s3));
}

// ---------------------------------------------------------------------------
// Kernel 2: champion GEMM + fused interior assembly (R10 main loop, verbatim).
// PDL: starts during prep_M, prefetches first A chunks to L2, then grid-syncs
// before reading g_M.
// ---------------------------------------------------------------------------
__device__ __forceinline__ uint32_t f2b2(float x, float y) {
    __nv_bfloat162 b = __floats2bfloat162_rn(x, y);
    return *reinterpret_cast<uint32_t*>(&b);
}

__global__ void __launch_bounds__(256, 2) gemm_k(const float* __restrict__ A,
                                                 const float* __restrict__ attn_bias,
                                                 const int*   __restrict__ spatial_pos,
                                                 const float* __restrict__ spatial_emb,
                                                 float*       __restrict__ out) {
    extern __shared__ __nv_bfloat16 Bs[];   // [32][SB]

    const int tid  = threadIdx.x;
    const int warp = tid >> 5;
    const int lane = tid & 31;
    const int q = lane >> 2;      // 0..7
    const int t = lane & 3;       // 0..3

    // ---- warm L2 with the first tile's first chunks while prep_M finishes ----
    {
        const int row0p = blockIdx.x * TILE_M + warp * 16;
        const float* p0 = A + (size_t)(row0p + q) * KTOT + t * 4;
        const float* p1 = p0 + (size_t)8 * KTOT;
#pragma unroll
        for (int u = 0; u < 4; u++) {
            asm volatile("prefetch.global.L2 [%0];" :: "l"(p0 + u * 16));
            asm volatile("prefetch.global.L2 [%0];" :: "l"(p1 + u * 16));
        }
    }
#if __CUDA_ARCH__ >= 900
    cudaGridDependencySynchronize();   // g_M (and ordering) from prep_M
#endif

    // ---- stage entire B once: 32 rows x 1280 bf16 (5120 uint4) ----
    {
        const uint4* src = (const uint4*)g_M;
#pragma unroll
        for (int i = 0; i < 20; i++) {
            int idx = tid + i * 256;            // 0..5119
            int g   = idx / 160;
            int c8  = idx - g * 160;
            uint4 v = src[(size_t)g * 160 + c8];
            *(uint4*)(Bs + g * SB + c8 * 8) = v;
        }
    }
    __syncthreads();   // only barrier in the kernel

    for (int w = 0; w < NTILES / NWORK; w++) {
        const int tile = blockIdx.x + w * NWORK;
        const int row0 = tile * TILE_M + warp * 16;

        const float* ap0 = A + (size_t)(row0 + q) * KTOT + t * 4;
        const float* ap1 = ap0 + (size_t)8 * KTOT;

        float acc[4][4];
#pragma unroll
        for (int i = 0; i < 4; i++)
#pragma unroll
            for (int j = 0; j < 4; j++) acc[i][j] = 0.f;

        float4 f[2][2][2];   // [buf][u][rowhalf]
        auto loadA = [&](float4 (&dst)[2][2], int kc) {
#pragma unroll
            for (int u = 0; u < 2; u++) {
                dst[u][0] = *(const float4*)(ap0 + kc + u * 16);
                dst[u][1] = *(const float4*)(ap1 + kc + u * 16);
            }
        };

        loadA(f[0], 0);
        loadA(f[1], 32);

#pragma unroll 2
        for (int s2 = 0; s2 < 40; s2++) {          // k32 steps, depth-2 pipeline
            const int kc  = s2 * 32;
            const int cur = s2 & 1;
            uint32_t a[2][4];
#pragma unroll
            for (int u = 0; u < 2; u++) {
                float4 fq  = f[cur][u][0];
                float4 fq8 = f[cur][u][1];
                a[u][0] = f2b2(fq.x,  fq.y);
                a[u][1] = f2b2(fq8.x, fq8.y);
                a[u][2] = f2b2(fq.z,  fq.w);
                a[u][3] = f2b2(fq8.z, fq8.w);
            }
            if (kc + 64 < KTOT) loadA(f[cur], kc + 64);
#pragma unroll
            for (int u = 0; u < 2; u++) {
                const int ks = kc + u * 16;
#pragma unroll
                for (int nb = 0; nb < 4; nb++) {
                    const __nv_bfloat16* bp = Bs + (nb * 8 + q) * SB + ks + t * 2;
                    uint32_t b0 = *(const uint32_t*)bp;
                    uint32_t b1 = *(const uint32_t*)(bp + 8);
                    asm volatile(
                        "mma.sync.aligned.m16n8k16.row.col.f32.bf16.bf16.f32 "
                        "{%0,%1,%2,%3}, {%4,%5,%6,%7}, {%8,%9}, {%0,%1,%2,%3};"
                        : "+f"(acc[nb][0]), "+f"(acc[nb][1]),
                          "+f"(acc[nb][2]), "+f"(acc[nb][3])
                        : "r"(a[u][0]), "r"(a[u][1]), "r"(a[u][2]), "r"(a[u][3]),
                          "r"(b0), "r"(b1));
                }
            }
        }

        // Fused epilogue: final output for the two rows this lane owns.
        const int rq = row0 + q;
#pragma unroll
        for (int rr = 0; rr < 2; rr++) {
            const int r  = rq + rr * 8;
            const int b  = r >> 12;
            const int ij = r & 4095;
            const int ii = ij >> 6;
            const int jj = ij & 63;
            float ab2 = 2.f * __ldg(&attn_bias[(b * NP1 + ii + 1) * NP1 + jj + 1]);
            int s = __ldg(&spatial_pos[r]);
            int sp = (s <= 1) ? 1 : (s - 1);
            sp = min(sp, 20);
            float inv = 1.f / (float)sp;
            const float* se = spatial_emb + (size_t)s * H_;
            float* ob = out + (size_t)b * H_ * CELLS + (size_t)(ii + 1) * NP1 + (jj + 1);
#pragma unroll
            for (int nb = 0; nb < 4; nb++) {
                const int g0 = nb * 8 + t * 2;
                float2 sev = *(const float2*)(se + g0);
                ob[(size_t)(g0 + 0) * CELLS] = ab2 + sev.x + acc[nb][rr * 2 + 0] * inv;
                ob[(size_t)(g0 + 1) * CELLS] = ab2 + sev.y + acc[nb][rr * 2 + 1] * inv;
            }
        }
        // no barrier between tiles: B immutable, warps independent
    }
}

// ---------------------------------------------------------------------------
extern "C" void kernel_launch(void* const* d_in, const int* in_sizes, int n_in,
                              void* d_out, int out_size) {
    // metadata order: node_features, attn_bias, spatial_pos, edge_input,
    //                 attn_edge_type, W_edge, spatial_emb, vd_weight, edge_dis_weight
    const float* attn_bias   = (const float*)d_in[1];
    const int*   spatial_pos = (const int*)  d_in[2];
    const float* edge_input  = (const float*)d_in[3];
    const float* W_edge      = (const float*)d_in[5];
    const float* spatial_emb = (const float*)d_in[6];
    const float* vd          = (const float*)d_in[7];
    const float* edw         = (const float*)d_in[8];
    float* out = (float*)d_out;

    static bool attr_set = false;
    if (!attr_set) {
        cudaFuncSetAttribute(gemm_k, cudaFuncAttributeMaxDynamicSharedMemorySize, SMEM_BYTES);
        attr_set = true;
    }

    // prep (160 blocks) + border (17 blocks)
    prep_M<<<160 + (B_ * 129 + 255) / 256, 256>>>(W_edge, edw, attn_bias, vd, out);

    // gemm with programmatic dependent launch: overlaps with prep_M's tail.
    cudaLaunchConfig_t cfg = {};
    cfg.gridDim  = dim3(NWORK, 1, 1);
    cfg.blockDim = dim3(256, 1, 1);
    cfg.dynamicSmemBytes = SMEM_BYTES;
    cfg.stream = 0;
    cudaLaunchAttribute at[1];
    at[0].id = cudaLaunchAttributeProgrammaticStreamSerialization;
    at[0].val.programmaticStreamSerializationAllowed = 1;
    cfg.attrs = at;
    cfg.numAttrs = 1;
    cudaError_t e = cudaLaunchKernelEx(&cfg, gemm_k, edge_input, attn_bias,
                                       spatial_pos, spatial_emb, out);
    if (e != cudaSuccess) {
        // fallback: plain launch (still correct, just serial)
        gemm_k<<<NWORK, 256, SMEM_BYTES>>>(edge_input, attn_bias, spatial_pos,
                                           spatial_emb, out);
    }
}

// round 15
// speedup vs baseline: 1.1806x; 1.0061x over previous
#include <cuda_runtime.h>
#include <cuda_bf16.h>
#include <cstdint>

// Problem constants
#define B_    32
#define N_    64
#define H_    32
#define KTOT  1280            // D*E
#define NROWS (B_*N_*N_)      // 131072
#define NP1   65
#define CELLS (NP1*NP1)       // 4225
#define TILE_M 128
#define NTILES (NROWS / TILE_M)   // 1024
#define NWORK  256                // static: 4 tiles per CTA (champion schedule)
#define SB    1288            // Bs row stride (bf16): (SB/2)%32==4 -> conflict-free
#define SMEM_BYTES (H_ * SB * 2)  // 82,432 B

// Scratch (allocation-free contract: device globals)
__device__ __nv_bfloat16 g_M[H_ * KTOT];   // 80 KB folded W3*W_edge, [g][k'] (k-permuted)

// ---------------------------------------------------------------------------
// Kernel 1 (merged): blocks < 160 compute g_M (8-way ILP on the h-chain);
// blocks >= 160 fill borders.
// ---------------------------------------------------------------------------
__global__ void prep_M(const float* __restrict__ W_edge, const float* __restrict__ edw,
                       const float* __restrict__ attn_bias, const float* __restrict__ vd,
                       float* __restrict__ out) {
    if (blockIdx.x >= 160) {
        int o = (blockIdx.x - 160) * blockDim.x + threadIdx.x;   // b*129 + c
        if (o >= B_ * 129) return;
        int c = o % 129;
        int b = o / 129;
        int i = (c < NP1) ? 0 : (c - 64);
        int j = (c < NP1) ? c : 0;
        float a2 = 2.f * attn_bias[(b * NP1 + i) * NP1 + j];
        float* op = out + (size_t)b * H_ * CELLS + (size_t)i * NP1 + j;
#pragma unroll 8
        for (int h = 0; h < H_; h++)
            op[(size_t)h * CELLS] = a2 + vd[h];
        return;
    }
    int idx = blockIdx.x * blockDim.x + threadIdx.x;
    if (idx >= H_ * KTOT) return;
    int g  = idx / KTOT;
    int kp = idx - g * KTOT;                 // permuted position k'
    int bse = kp & ~15;
    int b   = kp & 15;
    int o   = (b < 8) ? ((b >> 1) * 4 + (b & 1))
                      : (((b - 8) >> 1) * 4 + 2 + (b & 1));
    int k  = bse + o;                        // original k
    int dd = k >> 6;
    int e  = k & 63;
    float s[8];
#pragma unroll
    for (int x = 0; x < 8; x++) s[x] = 0.f;
#pragma unroll
    for (int h = 0; h < 32; h += 8) {
#pragma unroll
        for (int x = 0; x < 8; x++)
            s[x] += edw[dd * 1024 + (h + x) * 32 + g] * W_edge[(h + x) * 64 + e];
    }
    float r = ((s[0] + s[1]) + (s[2] + s[3])) + ((s[4] + s[5]) + (s[6] + s[7]));
    g_M[g * KTOT + kp] = __float2bfloat16(r);
}

// ---------------------------------------------------------------------------
// Kernel 2: champion GEMM + fused interior assembly (R10 main loop verbatim).
// PDL: pre-sync prefetch covers the first 4 k-chunks; epilogue uses streaming
// stores to keep L2 clean for the A stream.
// ---------------------------------------------------------------------------
__device__ __forceinline__ uint32_t f2b2(float x, float y) {
    __nv_bfloat162 b = __floats2bfloat162_rn(x, y);
    return *reinterpret_cast<uint32_t*>(&b);
}

__global__ void __launch_bounds__(256, 2) gemm_k(const float* __restrict__ A,
                                                 const float* __restrict__ attn_bias,
                                                 const int*   __restrict__ spatial_pos,
                                                 const float* __restrict__ spatial_emb,
                                                 float*       __restrict__ out) {
    extern __shared__ __nv_bfloat16 Bs[];   // [32][SB]

    const int tid  = threadIdx.x;
    const int warp = tid >> 5;
    const int lane = tid & 31;
    const int q = lane >> 2;      // 0..7
    const int t = lane & 3;       // 0..3

    // ---- pre-sync: warm L2 with the first 4 k-chunks of tile 0 ----
    {
        const int row0p = blockIdx.x * TILE_M + warp * 16;
        const float* p0 = A + (size_t)(row0p + q) * KTOT + t * 4;
        const float* p1 = p0 + (size_t)8 * KTOT;
#pragma unroll
        for (int u = 0; u < 8; u++) {
            asm volatile("prefetch.global.L2 [%0];" :: "l"(p0 + u * 16));
            asm volatile("prefetch.global.L2 [%0];" :: "l"(p1 + u * 16));
        }
    }
#if __CUDA_ARCH__ >= 900
    cudaGridDependencySynchronize();   // g_M (and ordering) from prep_M
#endif

    // ---- stage entire B once: 32 rows x 1280 bf16 (5120 uint4) ----
    {
        const uint4* src = (const uint4*)g_M;
#pragma unroll
        for (int i = 0; i < 20; i++) {
            int idx = tid + i * 256;            // 0..5119
            int g   = idx / 160;
            int c8  = idx - g * 160;
            uint4 v = src[(size_t)g * 160 + c8];
            *(uint4*)(Bs + g * SB + c8 * 8) = v;
        }
    }
    __syncthreads();   // only barrier in the kernel

    for (int w = 0; w < NTILES / NWORK; w++) {
        const int tile = blockIdx.x + w * NWORK;
        const int row0 = tile * TILE_M + warp * 16;

        const float* ap0 = A + (size_t)(row0 + q) * KTOT + t * 4;
        const float* ap1 = ap0 + (size_t)8 * KTOT;

        float acc[4][4];
#pragma unroll
        for (int i = 0; i < 4; i++)
#pragma unroll
            for (int j = 0; j < 4; j++) acc[i][j] = 0.f;

        float4 f[2][2][2];   // [buf][u][rowhalf]
        auto loadA = [&](float4 (&dst)[2][2], int kc) {
#pragma unroll
            for (int u = 0; u < 2; u++) {
                dst[u][0] = *(const float4*)(ap0 + kc + u * 16);
                dst[u][1] = *(const float4*)(ap1 + kc + u * 16);
            }
        };

        loadA(f[0], 0);
        loadA(f[1], 32);

#pragma unroll 2
        for (int s2 = 0; s2 < 40; s2++) {          // k32 steps, depth-2 pipeline
            const int kc  = s2 * 32;
            const int cur = s2 & 1;
            uint32_t a[2][4];
#pragma unroll
            for (int u = 0; u < 2; u++) {
                float4 fq  = f[cur][u][0];
                float4 fq8 = f[cur][u][1];
                a[u][0] = f2b2(fq.x,  fq.y);
                a[u][1] = f2b2(fq8.x, fq8.y);
                a[u][2] = f2b2(fq.z,  fq.w);
                a[u][3] = f2b2(fq8.z, fq8.w);
            }
            if (kc + 64 < KTOT) loadA(f[cur], kc + 64);
#pragma unroll
            for (int u = 0; u < 2; u++) {
                const int ks = kc + u * 16;
#pragma unroll
                for (int nb = 0; nb < 4; nb++) {
                    const __nv_bfloat16* bp = Bs + (nb * 8 + q) * SB + ks + t * 2;
                    uint32_t b0 = *(const uint32_t*)bp;
                    uint32_t b1 = *(const uint32_t*)(bp + 8);
                    asm volatile(
                        "mma.sync.aligned.m16n8k16.row.col.f32.bf16.bf16.f32 "
                        "{%0,%1,%2,%3}, {%4,%5,%6,%7}, {%8,%9}, {%0,%1,%2,%3};"
                        : "+f"(acc[nb][0]), "+f"(acc[nb][1]),
                          "+f"(acc[nb][2]), "+f"(acc[nb][3])
                        : "r"(a[u][0]), "r"(a[u][1]), "r"(a[u][2]), "r"(a[u][3]),
                          "r"(b0), "r"(b1));
                }
            }
        }

        // Fused epilogue: final output, streaming stores (write-once data).
        const int rq = row0 + q;
#pragma unroll
        for (int rr = 0; rr < 2; rr++) {
            const int r  = rq + rr * 8;
            const int b  = r >> 12;
            const int ij = r & 4095;
            const int ii = ij >> 6;
            const int jj = ij & 63;
            float ab2 = 2.f * __ldg(&attn_bias[(b * NP1 + ii + 1) * NP1 + jj + 1]);
            int s = __ldg(&spatial_pos[r]);
            int sp = (s <= 1) ? 1 : (s - 1);
            sp = min(sp, 20);
            float inv = 1.f / (float)sp;
            const float* se = spatial_emb + (size_t)s * H_;
            float* ob = out + (size_t)b * H_ * CELLS + (size_t)(ii + 1) * NP1 + (jj + 1);
#pragma unroll
            for (int nb = 0; nb < 4; nb++) {
                const int g0 = nb * 8 + t * 2;
                float2 sev = *(const float2*)(se + g0);
                __stcs(ob + (size_t)(g0 + 0) * CELLS, ab2 + sev.x + acc[nb][rr * 2 + 0] * inv);
                __stcs(ob + (size_t)(g0 + 1) * CELLS, ab2 + sev.y + acc[nb][rr * 2 + 1] * inv);
            }
        }
        // no barrier between tiles: B immutable, warps independent
    }
}

// ---------------------------------------------------------------------------
extern "C" void kernel_launch(void* const* d_in, const int* in_sizes, int n_in,
                              void* d_out, int out_size) {
    // metadata order: node_features, attn_bias, spatial_pos, edge_input,
    //                 attn_edge_type, W_edge, spatial_emb, vd_weight, edge_dis_weight
    const float* attn_bias   = (const float*)d_in[1];
    const int*   spatial_pos = (const int*)  d_in[2];
    const float* edge_input  = (const float*)d_in[3];
    const float* W_edge      = (const float*)d_in[5];
    const float* spatial_emb = (const float*)d_in[6];
    const float* vd          = (const float*)d_in[7];
    const float* edw         = (const float*)d_in[8];
    float* out = (float*)d_out;

    static bool attr_set = false;
    if (!attr_set) {
        cudaFuncSetAttribute(gemm_k, cudaFuncAttributeMaxDynamicSharedMemorySize, SMEM_BYTES);
        attr_set = true;
    }

    // prep (160 blocks) + border (17 blocks)
    prep_M<<<160 + (B_ * 129 + 255) / 256, 256>>>(W_edge, edw, attn_bias, vd, out);

    // gemm with programmatic dependent launch: overlaps with prep_M's tail.
    cudaLaunchConfig_t cfg = {};
    cfg.gridDim  = dim3(NWORK, 1, 1);
    cfg.blockDim = dim3(256, 1, 1);
    cfg.dynamicSmemBytes = SMEM_BYTES;
    cfg.stream = 0;
    cudaLaunchAttribute at[1];
    at[0].id = cudaLaunchAttributeProgrammaticStreamSerialization;
    at[0].val.programmaticStreamSerializationAllowed = 1;
    cfg.attrs = at;
    cfg.numAttrs = 1;
    cudaError_t e = cudaLaunchKernelEx(&cfg, gemm_k, edge_input, attn_bias,
                                       spatial_pos, spatial_emb, out);
    if (e != cudaSuccess) {
        gemm_k<<<NWORK, 256, SMEM_BYTES>>>(edge_input, attn_bias, spatial_pos,
                                           spatial_emb, out);
    }
}